// round 1
// baseline (speedup 1.0000x reference)
#include <cuda_runtime.h>

// ---------------------------------------------------------------------------
// CurveChannel: out[b,0,h,w] = clamp( sum_c conv_w[c] * sum_p slopes[p,c] *
//                              relu(x[b,c,h,w] - shift[p,c]) + conv_b, 0, 1 )
//
// Strategy: a 1-thread precompute kernel folds conv_w into the slopes and
// compacts the (slope != 0) breakpoints per channel into device globals.
// The main kernel is then a pure streaming pass: 3 float4 loads + 1 float4
// store per thread, with a tiny dynamic inner loop over the active
// breakpoints (1 per channel for the actual dataset).
// ---------------------------------------------------------------------------

#define NPTS 16
#define IN_CH 3
#define HHW   (512 * 512)       // per-channel plane, elements
#define HW4   (HHW / 4)         // per-channel plane, float4 groups

__device__ int   g_cnt[IN_CH];
__device__ float g_shift[IN_CH][NPTS];
__device__ float g_ws[IN_CH][NPTS];
__device__ float g_bias;

__global__ void curve_precompute(const float* __restrict__ shift,   // (NPTS, C)
                                 const float* __restrict__ slopes,  // (NPTS, C)
                                 const float* __restrict__ conv_w,  // (C,)
                                 const float* __restrict__ conv_b)  // (1,)
{
    // single thread: tiny, deterministic
    for (int c = 0; c < IN_CH; ++c) {
        float w = conv_w[c];
        int n = 0;
        for (int p = 0; p < NPTS; ++p) {
            float s = slopes[p * IN_CH + c];
            if (s != 0.0f) {
                g_shift[c][n] = shift[p * IN_CH + c];
                g_ws[c][n]    = s * w;
                ++n;
            }
        }
        g_cnt[c] = n;
    }
    g_bias = conv_b[0];
}

__global__ __launch_bounds__(256) void curve_main(const float* __restrict__ x,
                                                  float* __restrict__ out)
{
    __shared__ int   s_cnt[IN_CH];
    __shared__ float s_shift[IN_CH][NPTS];
    __shared__ float s_ws[IN_CH][NPTS];
    __shared__ float s_bias;

    int tid = threadIdx.x;
    if (tid < IN_CH * NPTS) {
        int c = tid / NPTS, p = tid % NPTS;
        s_shift[c][p] = g_shift[c][p];
        s_ws[c][p]    = g_ws[c][p];
    }
    if (tid < IN_CH) s_cnt[tid] = g_cnt[tid];
    if (tid == 0)    s_bias = g_bias;
    __syncthreads();

    // one float4 group of the (b, h, w) output per thread
    int g = blockIdx.x * blockDim.x + threadIdx.x;   // [0, 8*HW4)
    int b = g >> 16;            // g / HW4   (HW4 = 65536)
    int v = g & (HW4 - 1);      // g % HW4

    const float4* xb = reinterpret_cast<const float4*>(x) +
                       (size_t)b * (IN_CH * HW4);

    float bias = s_bias;
    float4 acc = make_float4(bias, bias, bias, bias);

    #pragma unroll
    for (int c = 0; c < IN_CH; ++c) {
        float4 xv = __ldg(&xb[c * HW4 + v]);
        int n = s_cnt[c];
        for (int j = 0; j < n; ++j) {
            float sh = s_shift[c][j];
            float w  = s_ws[c][j];
            acc.x = fmaf(w, fmaxf(xv.x - sh, 0.0f), acc.x);
            acc.y = fmaf(w, fmaxf(xv.y - sh, 0.0f), acc.y);
            acc.z = fmaf(w, fmaxf(xv.z - sh, 0.0f), acc.z);
            acc.w = fmaf(w, fmaxf(xv.w - sh, 0.0f), acc.w);
        }
    }

    acc.x = fminf(fmaxf(acc.x, 0.0f), 1.0f);
    acc.y = fminf(fmaxf(acc.y, 0.0f), 1.0f);
    acc.z = fminf(fmaxf(acc.z, 0.0f), 1.0f);
    acc.w = fminf(fmaxf(acc.w, 0.0f), 1.0f);

    reinterpret_cast<float4*>(out)[g] = acc;
}

extern "C" void kernel_launch(void* const* d_in, const int* in_sizes, int n_in,
                              void* d_out, int out_size)
{
    const float* x      = (const float*)d_in[0];  // (8, 3, 512, 512)
    const float* shift  = (const float*)d_in[1];  // (16, 3)
    const float* slopes = (const float*)d_in[2];  // (16, 3)
    const float* conv_w = (const float*)d_in[3];  // (3,)
    const float* conv_b = (const float*)d_in[4];  // (1,)
    float* out = (float*)d_out;                   // (8, 1, 512, 512)

    curve_precompute<<<1, 1>>>(shift, slopes, conv_w, conv_b);

    int total_groups = out_size / 4;              // 8 * 512*512 / 4 = 524288
    int threads = 256;
    int blocks = total_groups / threads;          // 2048
    curve_main<<<blocks, threads>>>(x, out);
}